// round 4
// baseline (speedup 1.0000x reference)
#include <cuda_runtime.h>
#include <math.h>

// Problem constants
#define BSZ   4096
#define LAT   64
#define FRAME 512
#define HID   1024
#define NE    8
#define GH    128
#define IN1   576    // LAT+FRAME
#define IN2   1088   // LAT+HID
#define NOUT  512

// ---------------- device scratch (static allocation; no cudaMalloc) -------
__device__ float g_coef[BSZ * NE];        // softmax gate coefs
__device__ float g_x0[BSZ * IN1];         // concat(z, c)
__device__ float g_xa[BSZ * IN2];         // concat(z, h0)  (layer0 out)
__device__ float g_xb[BSZ * IN2];         // concat(z, h1)  (layer1 out)

// ---------------- gate MLP -> softmax coef -------------------------------
#define GROWS 4
__global__ __launch_bounds__(128) void gate_kernel(
    const float* __restrict__ z, const float* __restrict__ c,
    const float* __restrict__ gw1, const float* __restrict__ gb1,
    const float* __restrict__ gw2, const float* __restrict__ gb2,
    const float* __restrict__ gw3, const float* __restrict__ gb3)
{
    __shared__ float sx[GROWS][IN1];
    __shared__ float sh[GROWS][GH];
    const int tid = threadIdx.x;            // 128 threads
    const int b0  = blockIdx.x * GROWS;

    for (int r = 0; r < GROWS; r++) {
        int b = b0 + r;
        for (int i = tid; i < LAT;   i += 128) sx[r][i]       = z[b * LAT + i];
        for (int i = tid; i < FRAME; i += 128) sx[r][LAT + i] = c[b * FRAME + i];
    }
    __syncthreads();

    // h1 = elu(x @ gw1 + gb1)
    float acc[GROWS];
    #pragma unroll
    for (int r = 0; r < GROWS; r++) acc[r] = gb1[tid];
    for (int i = 0; i < IN1; i++) {
        float g = gw1[i * GH + tid];
        #pragma unroll
        for (int r = 0; r < GROWS; r++) acc[r] += sx[r][i] * g;
    }
    #pragma unroll
    for (int r = 0; r < GROWS; r++)
        sh[r][tid] = acc[r] > 0.f ? acc[r] : expm1f(acc[r]);
    __syncthreads();

    // h2 = elu(h1 @ gw2 + gb2)
    float acc2[GROWS];
    #pragma unroll
    for (int r = 0; r < GROWS; r++) acc2[r] = gb2[tid];
    for (int i = 0; i < GH; i++) {
        float g = gw2[i * GH + tid];
        #pragma unroll
        for (int r = 0; r < GROWS; r++) acc2[r] += sh[r][i] * g;
    }
    __syncthreads();
    #pragma unroll
    for (int r = 0; r < GROWS; r++)
        sh[r][tid] = acc2[r] > 0.f ? acc2[r] : expm1f(acc2[r]);
    __syncthreads();

    // logits + softmax: one warp per row
    const int r = tid >> 5, lane = tid & 31;
    float lacc[NE];
    #pragma unroll
    for (int e = 0; e < NE; e++) lacc[e] = 0.f;
    for (int i = lane; i < GH; i += 32) {
        float h = sh[r][i];
        #pragma unroll
        for (int e = 0; e < NE; e++) lacc[e] += h * gw3[i * NE + e];
    }
    #pragma unroll
    for (int e = 0; e < NE; e++)
        #pragma unroll
        for (int o = 16; o > 0; o >>= 1)
            lacc[e] += __shfl_down_sync(0xffffffffu, lacc[e], o);
    if (lane == 0) {
        float logit[NE]; float mx = -1e30f;
        #pragma unroll
        for (int e = 0; e < NE; e++) { logit[e] = lacc[e] + gb3[e]; mx = fmaxf(mx, logit[e]); }
        float s = 0.f;
        #pragma unroll
        for (int e = 0; e < NE; e++) { logit[e] = expf(logit[e] - mx); s += logit[e]; }
        float inv = 1.f / s;
        int b = b0 + r;
        #pragma unroll
        for (int e = 0; e < NE; e++) g_coef[b * NE + e] = logit[e] * inv;
    }
}

// ------- fill x0 = concat(z,c) and the z-prefix of g_xa / g_xb -----------
__global__ void fill_kernel(const float* __restrict__ z, const float* __restrict__ c)
{
    int idx = blockIdx.x * blockDim.x + threadIdx.x;
    int nz = BSZ * (LAT / 4);
    if (idx < nz) {
        int b = idx / (LAT / 4), i4 = idx % (LAT / 4);
        float4 v = reinterpret_cast<const float4*>(&z[b * LAT])[i4];
        reinterpret_cast<float4*>(&g_x0[b * IN1])[i4] = v;
        reinterpret_cast<float4*>(&g_xa[b * IN2])[i4] = v;
        reinterpret_cast<float4*>(&g_xb[b * IN2])[i4] = v;
        return;
    }
    idx -= nz;
    int nc = BSZ * (FRAME / 4);
    if (idx < nc) {
        int b = idx / (FRAME / 4), i4 = idx % (FRAME / 4);
        float4 v = reinterpret_cast<const float4*>(&c[b * FRAME])[i4];
        reinterpret_cast<float4*>(&g_x0[b * IN1 + LAT])[i4] = v;
    }
}

// ---- fused-mix SGEMM: C[b,n] = sum_{e,i} coef[b,e] x[b,i] W[e*IN+i, n] ---
//      + sum_e coef[b,e] bias[e,n], optional ELU.
// A is synthesized on the fly from x (row stride xstride) and g_coef.
#define BM 128
#define BN 128
#define BK 8
#define TM 8
#define TN 8
__global__ __launch_bounds__(256) void gemm_kernel(
    const float* __restrict__ x, int xstride, int IN,
    const float* __restrict__ W,
    const float* __restrict__ bias,       // [NE, N]
    int N,
    float* __restrict__ out, int out_stride, int out_off, int do_elu)
{
    __shared__ float As[BK][BM];
    __shared__ float Bs[BK][BN];
    const int K = NE * IN;
    const int tid = threadIdx.x;
    const int bm = blockIdx.y * BM;
    const int bn = blockIdx.x * BN;

    // loaders: A tile 128x8 (one float4/thread), W tile 8x128
    const int arow = tid >> 1;
    const int acol = (tid & 1) * 4;
    const int brow = tid >> 5;
    const int bcol = (tid & 31) * 4;

    const int ty = tid >> 4;      // 8 rows each
    const int tx = tid & 15;      // 8 cols each

    float acc[TM][TN];
    #pragma unroll
    for (int i = 0; i < TM; i++)
        #pragma unroll
        for (int j = 0; j < TN; j++) acc[i][j] = 0.f;

    const float* xrow = x + (size_t)(bm + arow) * xstride;
    const float* crow = g_coef + (size_t)(bm + arow) * NE;
    const float* Wptr = W + (size_t)brow * N + bn + bcol;

    // synthesized-A fetch for K-offset k (BK-chunk never crosses an expert
    // boundary since IN % 8 == 0)
    auto fetchA = [&](int k, float4& a4) {
        int e = k / IN;
        int i = k - e * IN;
        float4 v = *reinterpret_cast<const float4*>(xrow + i);
        float cf = crow[e];
        a4 = make_float4(cf * v.x, cf * v.y, cf * v.z, cf * v.w);
    };

    float4 a4, b4;
    fetchA(acol, a4);
    b4 = *reinterpret_cast<const float4*>(Wptr);

    for (int k0 = 0; k0 < K; k0 += BK) {
        As[acol + 0][arow] = a4.x;
        As[acol + 1][arow] = a4.y;
        As[acol + 2][arow] = a4.z;
        As[acol + 3][arow] = a4.w;
        *reinterpret_cast<float4*>(&Bs[brow][bcol]) = b4;
        __syncthreads();

        int kn = k0 + BK;
        if (kn < K) {
            fetchA(kn + acol, a4);
            b4 = *reinterpret_cast<const float4*>(Wptr + (size_t)kn * N);
        }

        #pragma unroll
        for (int k = 0; k < BK; k++) {
            float4 a0 = *reinterpret_cast<const float4*>(&As[k][ty * TM]);
            float4 a1 = *reinterpret_cast<const float4*>(&As[k][ty * TM + 4]);
            float4 c0 = *reinterpret_cast<const float4*>(&Bs[k][tx * TN]);
            float4 c1 = *reinterpret_cast<const float4*>(&Bs[k][tx * TN + 4]);
            float ra[TM] = {a0.x, a0.y, a0.z, a0.w, a1.x, a1.y, a1.z, a1.w};
            float rb[TN] = {c0.x, c0.y, c0.z, c0.w, c1.x, c1.y, c1.z, c1.w};
            #pragma unroll
            for (int i = 0; i < TM; i++)
                #pragma unroll
                for (int j = 0; j < TN; j++) acc[i][j] += ra[i] * rb[j];
        }
        __syncthreads();
    }

    // epilogue: mixed bias + optional ELU
    #pragma unroll
    for (int i = 0; i < TM; i++) {
        int row = bm + ty * TM + i;
        float cf[NE];
        #pragma unroll
        for (int e = 0; e < NE; e++) cf[e] = g_coef[row * NE + e];
        #pragma unroll
        for (int j = 0; j < TN; j++) {
            int col = bn + tx * TN + j;
            float v = acc[i][j];
            #pragma unroll
            for (int e = 0; e < NE; e++) v += cf[e] * bias[e * N + col];
            if (do_elu) v = v > 0.f ? v : expm1f(v);
            out[(size_t)row * out_stride + out_off + col] = v;
        }
    }
}

// ---------------- launch ---------------------------------------------------
extern "C" void kernel_launch(void* const* d_in, const int* in_sizes, int n_in,
                              void* d_out, int out_size)
{
    const float* z   = (const float*)d_in[0];
    const float* c   = (const float*)d_in[1];
    const float* w0  = (const float*)d_in[2];
    const float* b0  = (const float*)d_in[3];
    const float* w1  = (const float*)d_in[4];
    const float* b1  = (const float*)d_in[5];
    const float* w2  = (const float*)d_in[6];
    const float* b2  = (const float*)d_in[7];
    const float* gw1 = (const float*)d_in[8];
    const float* gb1 = (const float*)d_in[9];
    const float* gw2 = (const float*)d_in[10];
    const float* gb2 = (const float*)d_in[11];
    const float* gw3 = (const float*)d_in[12];
    const float* gb3 = (const float*)d_in[13];
    float* out = (float*)d_out;

    float* x0; cudaGetSymbolAddress((void**)&x0, g_x0);
    float* xa; cudaGetSymbolAddress((void**)&xa, g_xa);
    float* xb; cudaGetSymbolAddress((void**)&xb, g_xb);

    // gate -> coef
    gate_kernel<<<BSZ / GROWS, 128>>>(z, c, gw1, gb1, gw2, gb2, gw3, gb3);

    // concat buffers (z prefixes + c suffix)
    {
        int total = BSZ * (LAT / 4) + BSZ * (FRAME / 4);
        fill_kernel<<<(total + 255) / 256, 256>>>(z, c);
    }

    // ---- layer 0: x = x0 [B, IN1], K = 4608, N = HID, out -> g_xa[:, LAT:] ----
    {
        dim3 grid(HID / BN, BSZ / BM);
        gemm_kernel<<<grid, 256>>>(x0, IN1, IN1, w0, b0, HID,
                                   xa, IN2, LAT, /*elu=*/1);
    }
    // ---- layer 1: x = g_xa [B, IN2], K = 8704, N = HID, out -> g_xb[:, LAT:] ----
    {
        dim3 grid(HID / BN, BSZ / BM);
        gemm_kernel<<<grid, 256>>>(xa, IN2, IN2, w1, b1, HID,
                                   xb, IN2, LAT, /*elu=*/1);
    }
    // ---- layer 2: x = g_xb [B, IN2], K = 8704, N = NOUT, out -> d_out ----
    {
        dim3 grid(NOUT / BN, BSZ / BM);
        gemm_kernel<<<grid, 256>>>(xb, IN2, IN2, w2, b2, NOUT,
                                   out, NOUT, 0, /*elu=*/0);
    }
}

// round 6
// speedup vs baseline: 2.8435x; 2.8435x over previous
#include <cuda_runtime.h>
#include <cuda_bf16.h>
#include <math.h>
#include <stdint.h>

// Problem constants
#define BSZ   4096
#define LAT   64
#define FRAME 512
#define HID   1024
#define NE    8
#define GH    128
#define IN1   576    // LAT+FRAME
#define IN2   1088   // LAT+HID
#define NOUT  512
#define K0R   (NE*IN1)    // 4608
#define K12R  (NE*IN2)    // 8704
#define K0P   (K0R + 32)  // 4640  (bias fold + pad)
#define K12P  (K12R + 32) // 8736

// ---------------- device scratch (static; no cudaMalloc) ------------------
__device__ float g_coef[BSZ * NE];
__device__ float g_x0[BSZ * IN1];                    // concat(z, c)
__device__ float g_xa[BSZ * IN2];                    // concat(z, h0)
__device__ float g_xb[BSZ * IN2];                    // concat(z, h1)
__device__ __nv_bfloat16 g_wth[(size_t)HID * K12P]; // weight^T hi (bf16)
__device__ __nv_bfloat16 g_wtl[(size_t)HID * K12P]; // weight^T lo (bf16)

// ======================= PTX helpers (plain sm_103-safe) ==================
__device__ __forceinline__ uint32_t smem_u32(const void* p) {
    uint32_t a;
    asm("{ .reg .u64 t; cvta.to.shared.u64 t, %1; cvt.u32.u64 %0, t; }"
        : "=r"(a) : "l"(p));
    return a;
}

#define LDSM_X4(r0, r1, r2, r3, addr) \
    asm volatile("ldmatrix.sync.aligned.m8n8.x4.shared.b16 {%0,%1,%2,%3}, [%4];" \
                 : "=r"(r0), "=r"(r1), "=r"(r2), "=r"(r3) : "r"(addr))

#define MMA_BF16(c, a, b) \
    asm volatile("mma.sync.aligned.m16n8k16.row.col.f32.bf16.bf16.f32 " \
                 "{%0,%1,%2,%3}, {%4,%5,%6,%7}, {%8,%9}, {%0,%1,%2,%3};" \
                 : "+f"((c)[0]), "+f"((c)[1]), "+f"((c)[2]), "+f"((c)[3]) \
                 : "r"((a)[0]), "r"((a)[1]), "r"((a)[2]), "r"((a)[3]), \
                   "r"((b)[0]), "r"((b)[1]))

// ======================= gate MLP -> softmax coef =========================
#define GROWS 4
__global__ __launch_bounds__(128) void gate_kernel(
    const float* __restrict__ z, const float* __restrict__ c,
    const float* __restrict__ gw1, const float* __restrict__ gb1,
    const float* __restrict__ gw2, const float* __restrict__ gb2,
    const float* __restrict__ gw3, const float* __restrict__ gb3)
{
    __shared__ float sx[GROWS][IN1];
    __shared__ float sh[GROWS][GH];
    const int tid = threadIdx.x;
    const int b0  = blockIdx.x * GROWS;

    for (int r = 0; r < GROWS; r++) {
        int b = b0 + r;
        for (int i = tid; i < LAT;   i += 128) sx[r][i]       = z[b * LAT + i];
        for (int i = tid; i < FRAME; i += 128) sx[r][LAT + i] = c[b * FRAME + i];
    }
    __syncthreads();

    float acc[GROWS];
    #pragma unroll
    for (int r = 0; r < GROWS; r++) acc[r] = gb1[tid];
    for (int i = 0; i < IN1; i++) {
        float g = gw1[i * GH + tid];
        #pragma unroll
        for (int r = 0; r < GROWS; r++) acc[r] += sx[r][i] * g;
    }
    #pragma unroll
    for (int r = 0; r < GROWS; r++)
        sh[r][tid] = acc[r] > 0.f ? acc[r] : expm1f(acc[r]);
    __syncthreads();

    float acc2[GROWS];
    #pragma unroll
    for (int r = 0; r < GROWS; r++) acc2[r] = gb2[tid];
    for (int i = 0; i < GH; i++) {
        float g = gw2[i * GH + tid];
        #pragma unroll
        for (int r = 0; r < GROWS; r++) acc2[r] += sh[r][i] * g;
    }
    __syncthreads();
    #pragma unroll
    for (int r = 0; r < GROWS; r++)
        sh[r][tid] = acc2[r] > 0.f ? acc2[r] : expm1f(acc2[r]);
    __syncthreads();

    const int r = tid >> 5, lane = tid & 31;
    float lacc[NE];
    #pragma unroll
    for (int e = 0; e < NE; e++) lacc[e] = 0.f;
    for (int i = lane; i < GH; i += 32) {
        float h = sh[r][i];
        #pragma unroll
        for (int e = 0; e < NE; e++) lacc[e] += h * gw3[i * NE + e];
    }
    #pragma unroll
    for (int e = 0; e < NE; e++)
        #pragma unroll
        for (int o = 16; o > 0; o >>= 1)
            lacc[e] += __shfl_down_sync(0xffffffffu, lacc[e], o);
    if (lane == 0) {
        float logit[NE]; float mx = -1e30f;
        #pragma unroll
        for (int e = 0; e < NE; e++) { logit[e] = lacc[e] + gb3[e]; mx = fmaxf(mx, logit[e]); }
        float s = 0.f;
        #pragma unroll
        for (int e = 0; e < NE; e++) { logit[e] = expf(logit[e] - mx); s += logit[e]; }
        float inv = 1.f / s;
        int b = b0 + r;
        #pragma unroll
        for (int e = 0; e < NE; e++) g_coef[b * NE + e] = logit[e] * inv;
    }
}

// ---- fill x0 = concat(z,c), z prefixes of g_xa/g_xb ----------------------
__global__ void fill_kernel(const float* __restrict__ z, const float* __restrict__ c)
{
    int idx = blockIdx.x * blockDim.x + threadIdx.x;
    int nz = BSZ * (LAT / 4);
    if (idx < nz) {
        int b = idx / (LAT / 4), i4 = idx % (LAT / 4);
        float4 v = reinterpret_cast<const float4*>(&z[b * LAT])[i4];
        reinterpret_cast<float4*>(&g_x0[b * IN1])[i4] = v;
        reinterpret_cast<float4*>(&g_xa[b * IN2])[i4] = v;
        reinterpret_cast<float4*>(&g_xb[b * IN2])[i4] = v;
        return;
    }
    idx -= nz;
    int nc = BSZ * (FRAME / 4);
    if (idx < nc) {
        int b = idx / (FRAME / 4), i4 = idx % (FRAME / 4);
        float4 v = reinterpret_cast<const float4*>(&c[b * FRAME])[i4];
        reinterpret_cast<float4*>(&g_x0[b * IN1 + LAT])[i4] = v;
    }
}

// ---- weight prep: Wt hi/lo bf16.  g_wt*[n][k] = split(W[k][n]) (k<K);
//      bias[e][n] at k=K+e; zero pad to Kpad. ---------------------------
__global__ __launch_bounds__(256) void prep_kernel(
    const float* __restrict__ W, const float* __restrict__ bias,
    int K, int N, int Kpad)
{
    __shared__ float ts[32][33];
    const int kx = blockIdx.x, ny = blockIdx.y;
    const int tx = threadIdx.x & 31, ty = threadIdx.x >> 5;  // 32 x 8
    const int n0 = ny * 32;
    const int Kt = K / 32;
    if (kx < Kt) {
        const int k0 = kx * 32;
        #pragma unroll
        for (int rr = 0; rr < 4; rr++) {
            int k = k0 + ty + rr * 8;
            ts[ty + rr * 8][tx] = W[(size_t)k * N + n0 + tx];
        }
        __syncthreads();
        #pragma unroll
        for (int rr = 0; rr < 4; rr++) {
            int n = n0 + ty + rr * 8;
            float v = ts[tx][ty + rr * 8];
            __nv_bfloat16 h = __float2bfloat16(v);
            float lo = v - __bfloat162float(h);
            g_wth[(size_t)n * Kpad + k0 + tx] = h;
            g_wtl[(size_t)n * Kpad + k0 + tx] = __float2bfloat16(lo);
        }
    } else {
        #pragma unroll
        for (int rr = 0; rr < 4; rr++) {
            int n = n0 + ty + rr * 8;
            float v = (tx < NE) ? bias[tx * N + n] : 0.f;
            __nv_bfloat16 h = __float2bfloat16(v);
            float lo = v - __bfloat162float(h);
            g_wth[(size_t)n * Kpad + K + tx] = h;
            g_wtl[(size_t)n * Kpad + K + tx] = __float2bfloat16(lo);
        }
    }
}

// ======== split-bf16 mma.sync GEMM: BM=BN=128, BK=32, 256 threads =========
// C[b,n] = sum_k A[b,k] Wt[n,k];  A synthesized: coef*x (k<Kreal),
// coef (bias fold zone), 0 pad.  3-term split: AhBh + AhBl + AlBh.
#define BMg 128
#define BNg 128
#define BKg 32
#define APITCH 40                 // bf16 units per smem row (80B, conflict-free)
#define TILE_BF (128 * APITCH)    // 5120 bf16 = 10240 B
#define STAGE_BF (4 * TILE_BF)    // Ah, Al, Bh, Bl
#define SMEM_BYTES (2 * STAGE_BF * 2)   // 81920

__global__ __launch_bounds__(256) void gemm_mma_kernel(
    const float* __restrict__ x, int xstride, int INw,
    int Kreal, int Kpad,
    const __nv_bfloat16* __restrict__ wth,
    const __nv_bfloat16* __restrict__ wtl,
    float* __restrict__ out, int out_stride, int out_off, int do_elu)
{
    extern __shared__ __nv_bfloat16 smem[];
    const uint32_t sb = smem_u32(smem);
    const int tid  = threadIdx.x;
    const int lane = tid & 31;
    const int wid  = tid >> 5;
    const int warp_m = wid & 3;        // 4 along M (32 rows each)
    const int warp_n = wid >> 2;       // 2 along N (64 cols each)
    const int bm = blockIdx.y * BMg;
    const int bn = blockIdx.x * BNg;

    // loader mapping: t in [0,1024): row = t>>3 (128), q = t&7 (8 float4 = 32 k)
    const int lrow = tid >> 1;             // wait: need 4 iterations of 256
    (void)lrow;

    float C[2][8][4];
    #pragma unroll
    for (int tm = 0; tm < 2; tm++)
        #pragma unroll
        for (int tn = 0; tn < 8; tn++)
            #pragma unroll
            for (int u = 0; u < 4; u++) C[tm][tn][u] = 0.f;

    // ldmatrix per-lane offsets (bytes)
    const int a_r  = (lane & 7) + ((lane >> 3) & 1) * 8;
    const int a_ko = (lane >> 4) * 16;
    const uint32_t aoff = a_r * (APITCH * 2) + a_ko;
    const int b_r  = (lane & 7) + (lane >> 4) * 8;
    const int b_ko = ((lane >> 3) & 1) * 16;
    const uint32_t boff = b_r * (APITCH * 2) + b_ko;

    const int niter = Kpad / BKg;

    // prefetch regs
    float4 va[4];
    uint2  vbh[4], vbl[4];

    auto loadAB = [&](int it) {
        const int k0 = it * BKg;
        const bool ezone = (k0 < Kreal);
        int e = 0, ib = 0;
        if (ezone) { e = k0 / INw; ib = k0 - e * INw; }
        #pragma unroll
        for (int j = 0; j < 4; j++) {
            int t = tid + j * 256;
            int row = t >> 3, q = t & 7;
            if (ezone) {
                float4 v = *reinterpret_cast<const float4*>(
                    x + (size_t)(bm + row) * xstride + ib + q * 4);
                float cf = g_coef[(bm + row) * NE + e];
                va[j] = make_float4(cf * v.x, cf * v.y, cf * v.z, cf * v.w);
            } else {
                int kg = k0 + q * 4;
                float av[4];
                #pragma unroll
                for (int u = 0; u < 4; u++) {
                    int d = kg + u - Kreal;
                    av[u] = (d >= 0 && d < NE) ? g_coef[(bm + row) * NE + d] : 0.f;
                }
                va[j] = make_float4(av[0], av[1], av[2], av[3]);
            }
            vbh[j] = *reinterpret_cast<const uint2*>(
                wth + (size_t)(bn + row) * Kpad + k0 + q * 4);
            vbl[j] = *reinterpret_cast<const uint2*>(
                wtl + (size_t)(bn + row) * Kpad + k0 + q * 4);
        }
    };

    loadAB(0);

    for (int i = 0; i < niter; i++) {
        const int s = i & 1;
        __nv_bfloat16* Ah = smem + s * STAGE_BF;
        __nv_bfloat16* Al = Ah + TILE_BF;
        __nv_bfloat16* Bh = Al + TILE_BF;
        __nv_bfloat16* Bl = Bh + TILE_BF;

        // store prefetched tile (split A on the fly)
        #pragma unroll
        for (int j = 0; j < 4; j++) {
            int t = tid + j * 256;
            int row = t >> 3, q = t & 7;
            int so = row * APITCH + q * 4;
            float4 a = va[j];
            __nv_bfloat162 h01 = __floats2bfloat162_rn(a.x, a.y);
            __nv_bfloat162 h23 = __floats2bfloat162_rn(a.z, a.w);
            float l0 = a.x - __bfloat162float(h01.x);
            float l1 = a.y - __bfloat162float(h01.y);
            float l2 = a.z - __bfloat162float(h23.x);
            float l3 = a.w - __bfloat162float(h23.y);
            __nv_bfloat162 lo01 = __floats2bfloat162_rn(l0, l1);
            __nv_bfloat162 lo23 = __floats2bfloat162_rn(l2, l3);
            uint2 hh, ll;
            hh.x = *reinterpret_cast<uint32_t*>(&h01);
            hh.y = *reinterpret_cast<uint32_t*>(&h23);
            ll.x = *reinterpret_cast<uint32_t*>(&lo01);
            ll.y = *reinterpret_cast<uint32_t*>(&lo23);
            *reinterpret_cast<uint2*>(Ah + so) = hh;
            *reinterpret_cast<uint2*>(Al + so) = ll;
            *reinterpret_cast<uint2*>(Bh + so) = vbh[j];
            *reinterpret_cast<uint2*>(Bl + so) = vbl[j];
        }
        __syncthreads();

        if (i + 1 < niter) loadAB(i + 1);

        const uint32_t sAh = sb + (uint32_t)(s * STAGE_BF) * 2;
        const uint32_t sAl = sAh + TILE_BF * 2;
        const uint32_t sBh = sAl + TILE_BF * 2;
        const uint32_t sBl = sBh + TILE_BF * 2;

        #pragma unroll
        for (int ks = 0; ks < 2; ks++) {
            uint32_t ah[2][4], al[2][4], bh[4][4], bl[4][4];
            #pragma unroll
            for (int tm = 0; tm < 2; tm++) {
                uint32_t base = (warp_m * 32 + tm * 16) * (APITCH * 2) + ks * 32;
                LDSM_X4(ah[tm][0], ah[tm][1], ah[tm][2], ah[tm][3], sAh + base + aoff);
                LDSM_X4(al[tm][0], al[tm][1], al[tm][2], al[tm][3], sAl + base + aoff);
            }
            #pragma unroll
            for (int g = 0; g < 4; g++) {
                uint32_t base = (warp_n * 64 + g * 16) * (APITCH * 2) + ks * 32;
                LDSM_X4(bh[g][0], bh[g][1], bh[g][2], bh[g][3], sBh + base + boff);
                LDSM_X4(bl[g][0], bl[g][1], bl[g][2], bl[g][3], sBl + base + boff);
            }
            #pragma unroll
            for (int tm = 0; tm < 2; tm++)
                #pragma unroll
                for (int tn = 0; tn < 8; tn++) {
                    const uint32_t* bph = &bh[tn >> 1][(tn & 1) * 2];
                    const uint32_t* bpl = &bl[tn >> 1][(tn & 1) * 2];
                    MMA_BF16(C[tm][tn], ah[tm], bph);
                    MMA_BF16(C[tm][tn], ah[tm], bpl);
                    MMA_BF16(C[tm][tn], al[tm], bph);
                }
        }
    }

    // ---- epilogue ----
    #pragma unroll
    for (int tm = 0; tm < 2; tm++) {
        int m0 = bm + warp_m * 32 + tm * 16 + (lane >> 2);
        #pragma unroll
        for (int tn = 0; tn < 8; tn++) {
            int n0 = bn + warp_n * 64 + tn * 8 + (lane & 3) * 2;
            float2 v0 = make_float2(C[tm][tn][0], C[tm][tn][1]);
            float2 v1 = make_float2(C[tm][tn][2], C[tm][tn][3]);
            if (do_elu) {
                v0.x = v0.x > 0.f ? v0.x : expm1f(v0.x);
                v0.y = v0.y > 0.f ? v0.y : expm1f(v0.y);
                v1.x = v1.x > 0.f ? v1.x : expm1f(v1.x);
                v1.y = v1.y > 0.f ? v1.y : expm1f(v1.y);
            }
            *reinterpret_cast<float2*>(out + (size_t)m0 * out_stride + out_off + n0) = v0;
            *reinterpret_cast<float2*>(out + (size_t)(m0 + 8) * out_stride + out_off + n0) = v1;
        }
    }
}

// ================================ launch ==================================
extern "C" void kernel_launch(void* const* d_in, const int* in_sizes, int n_in,
                              void* d_out, int out_size)
{
    const float* z   = (const float*)d_in[0];
    const float* c   = (const float*)d_in[1];
    const float* w0  = (const float*)d_in[2];
    const float* b0  = (const float*)d_in[3];
    const float* w1  = (const float*)d_in[4];
    const float* b1  = (const float*)d_in[5];
    const float* w2  = (const float*)d_in[6];
    const float* b2  = (const float*)d_in[7];
    const float* gw1 = (const float*)d_in[8];
    const float* gb1 = (const float*)d_in[9];
    const float* gw2 = (const float*)d_in[10];
    const float* gb2 = (const float*)d_in[11];
    const float* gw3 = (const float*)d_in[12];
    const float* gb3 = (const float*)d_in[13];
    float* out = (float*)d_out;

    float* x0; cudaGetSymbolAddress((void**)&x0, g_x0);
    float* xa; cudaGetSymbolAddress((void**)&xa, g_xa);
    float* xb; cudaGetSymbolAddress((void**)&xb, g_xb);
    __nv_bfloat16* wth; cudaGetSymbolAddress((void**)&wth, g_wth);
    __nv_bfloat16* wtl; cudaGetSymbolAddress((void**)&wtl, g_wtl);

    cudaFuncSetAttribute(gemm_mma_kernel,
                         cudaFuncAttributeMaxDynamicSharedMemorySize, SMEM_BYTES);

    // gate -> coef ; concat buffers
    gate_kernel<<<BSZ / GROWS, 128>>>(z, c, gw1, gb1, gw2, gb2, gw3, gb3);
    {
        int total = BSZ * (LAT / 4) + BSZ * (FRAME / 4);
        fill_kernel<<<(total + 255) / 256, 256>>>(z, c);
    }

    // ---- layer 0: K=4608(+32), N=HID ----
    {
        dim3 pg(K0R / 32 + 1, HID / 32);
        prep_kernel<<<pg, 256>>>(w0, b0, K0R, HID, K0P);
        dim3 grid(HID / BNg, BSZ / BMg);
        gemm_mma_kernel<<<grid, 256, SMEM_BYTES>>>(x0, IN1, IN1, K0R, K0P,
                                                   wth, wtl, xa, IN2, LAT, 1);
    }
    // ---- layer 1: K=8704(+32), N=HID ----
    {
        dim3 pg(K12R / 32 + 1, HID / 32);
        prep_kernel<<<pg, 256>>>(w1, b1, K12R, HID, K12P);
        dim3 grid(HID / BNg, BSZ / BMg);
        gemm_mma_kernel<<<grid, 256, SMEM_BYTES>>>(xa, IN2, IN2, K12R, K12P,
                                                   wth, wtl, xb, IN2, LAT, 1);
    }
    // ---- layer 2: K=8704(+32), N=NOUT ----
    {
        dim3 pg(K12R / 32 + 1, NOUT / 32);
        prep_kernel<<<pg, 256>>>(w2, b2, K12R, NOUT, K12P);
        dim3 grid(NOUT / BNg, BSZ / BMg);
        gemm_mma_kernel<<<grid, 256, SMEM_BYTES>>>(xb, IN2, IN2, K12R, K12P,
                                                   wth, wtl, out, NOUT, 0, 0);
    }
}

// round 7
// speedup vs baseline: 3.9417x; 1.3862x over previous
#include <cuda_runtime.h>
#include <cuda_bf16.h>
#include <math.h>
#include <stdint.h>

// Problem constants
#define BSZ   4096
#define LAT   64
#define FRAME 512
#define HID   1024
#define NE    8
#define GH    128
#define IN1   576    // LAT+FRAME
#define IN2   1088   // LAT+HID
#define NOUT  512

// ---------------- device scratch (static; no cudaMalloc) ------------------
__device__ float g_coef[BSZ * NE];
__device__ __nv_bfloat16 g_xh0[BSZ * IN1], g_xl0[BSZ * IN1]; // concat(z,c) hi/lo
__device__ __nv_bfloat16 g_xh [BSZ * IN2], g_xl [BSZ * IN2]; // concat(z,h) hi/lo
__device__ __nv_bfloat16 g_wth[(size_t)(NE * HID) * IN2];    // W^T hi  (17.8MB)
__device__ __nv_bfloat16 g_wtl[(size_t)(NE * HID) * IN2];    // W^T lo
__device__ float g_Y[(size_t)BSZ * NE * HID];                // per-expert outputs (134MB)

// ======================= PTX helpers (plain sm_103-safe) ==================
__device__ __forceinline__ uint32_t smem_u32(const void* p) {
    uint32_t a;
    asm("{ .reg .u64 t; cvta.to.shared.u64 t, %1; cvt.u32.u64 %0, t; }"
        : "=r"(a) : "l"(p));
    return a;
}
#define LDSM_X4(r0, r1, r2, r3, addr) \
    asm volatile("ldmatrix.sync.aligned.m8n8.x4.shared.b16 {%0,%1,%2,%3}, [%4];" \
                 : "=r"(r0), "=r"(r1), "=r"(r2), "=r"(r3) : "r"(addr))
#define MMA_BF16(c, a, b) \
    asm volatile("mma.sync.aligned.m16n8k16.row.col.f32.bf16.bf16.f32 " \
                 "{%0,%1,%2,%3}, {%4,%5,%6,%7}, {%8,%9}, {%0,%1,%2,%3};" \
                 : "+f"((c)[0]), "+f"((c)[1]), "+f"((c)[2]), "+f"((c)[3]) \
                 : "r"((a)[0]), "r"((a)[1]), "r"((a)[2]), "r"((a)[3]), \
                   "r"((b)[0]), "r"((b)[1]))
#define CP_ASYNC16(dst, src) \
    asm volatile("cp.async.cg.shared.global [%0], [%1], 16;" :: "r"(dst), "l"(src))
#define CP_COMMIT() asm volatile("cp.async.commit_group;" ::: "memory")
#define CP_WAIT1()  asm volatile("cp.async.wait_group 1;" ::: "memory")

__device__ __forceinline__ void split4(float4 a, uint2& h, uint2& l) {
    __nv_bfloat162 h01 = __floats2bfloat162_rn(a.x, a.y);
    __nv_bfloat162 h23 = __floats2bfloat162_rn(a.z, a.w);
    __nv_bfloat162 l01 = __floats2bfloat162_rn(a.x - __bfloat162float(h01.x),
                                               a.y - __bfloat162float(h01.y));
    __nv_bfloat162 l23 = __floats2bfloat162_rn(a.z - __bfloat162float(h23.x),
                                               a.w - __bfloat162float(h23.y));
    h.x = *reinterpret_cast<uint32_t*>(&h01);
    h.y = *reinterpret_cast<uint32_t*>(&h23);
    l.x = *reinterpret_cast<uint32_t*>(&l01);
    l.y = *reinterpret_cast<uint32_t*>(&l23);
}

// ======================= gate MLP -> softmax coef =========================
#define GROWS 4
__global__ __launch_bounds__(128) void gate_kernel(
    const float* __restrict__ z, const float* __restrict__ c,
    const float* __restrict__ gw1, const float* __restrict__ gb1,
    const float* __restrict__ gw2, const float* __restrict__ gb2,
    const float* __restrict__ gw3, const float* __restrict__ gb3)
{
    __shared__ float sx[GROWS][IN1];
    __shared__ float sh[GROWS][GH];
    const int tid = threadIdx.x;
    const int b0  = blockIdx.x * GROWS;

    for (int r = 0; r < GROWS; r++) {
        int b = b0 + r;
        for (int i = tid; i < LAT;   i += 128) sx[r][i]       = z[b * LAT + i];
        for (int i = tid; i < FRAME; i += 128) sx[r][LAT + i] = c[b * FRAME + i];
    }
    __syncthreads();

    float acc[GROWS];
    #pragma unroll
    for (int r = 0; r < GROWS; r++) acc[r] = gb1[tid];
    for (int i = 0; i < IN1; i++) {
        float g = gw1[i * GH + tid];
        #pragma unroll
        for (int r = 0; r < GROWS; r++) acc[r] += sx[r][i] * g;
    }
    #pragma unroll
    for (int r = 0; r < GROWS; r++)
        sh[r][tid] = acc[r] > 0.f ? acc[r] : expm1f(acc[r]);
    __syncthreads();

    float acc2[GROWS];
    #pragma unroll
    for (int r = 0; r < GROWS; r++) acc2[r] = gb2[tid];
    for (int i = 0; i < GH; i++) {
        float g = gw2[i * GH + tid];
        #pragma unroll
        for (int r = 0; r < GROWS; r++) acc2[r] += sh[r][i] * g;
    }
    __syncthreads();
    #pragma unroll
    for (int r = 0; r < GROWS; r++)
        sh[r][tid] = acc2[r] > 0.f ? acc2[r] : expm1f(acc2[r]);
    __syncthreads();

    const int r = tid >> 5, lane = tid & 31;
    float lacc[NE];
    #pragma unroll
    for (int e = 0; e < NE; e++) lacc[e] = 0.f;
    for (int i = lane; i < GH; i += 32) {
        float h = sh[r][i];
        #pragma unroll
        for (int e = 0; e < NE; e++) lacc[e] += h * gw3[i * NE + e];
    }
    #pragma unroll
    for (int e = 0; e < NE; e++)
        #pragma unroll
        for (int o = 16; o > 0; o >>= 1)
            lacc[e] += __shfl_down_sync(0xffffffffu, lacc[e], o);
    if (lane == 0) {
        float logit[NE]; float mx = -1e30f;
        #pragma unroll
        for (int e = 0; e < NE; e++) { logit[e] = lacc[e] + gb3[e]; mx = fmaxf(mx, logit[e]); }
        float s = 0.f;
        #pragma unroll
        for (int e = 0; e < NE; e++) { logit[e] = expf(logit[e] - mx); s += logit[e]; }
        float inv = 1.f / s;
        int b = b0 + r;
        #pragma unroll
        for (int e = 0; e < NE; e++) g_coef[b * NE + e] = logit[e] * inv;
    }
}

// ---- fill: split z into xh0/xl0 + xh/xl prefixes; c into xh0/xl0 suffix --
__global__ void fill_kernel(const float* __restrict__ z, const float* __restrict__ c)
{
    int idx = blockIdx.x * blockDim.x + threadIdx.x;
    int nz = BSZ * (LAT / 4);
    if (idx < nz) {
        int b = idx / (LAT / 4), i4 = idx % (LAT / 4);
        float4 v = reinterpret_cast<const float4*>(&z[b * LAT])[i4];
        uint2 h, l; split4(v, h, l);
        reinterpret_cast<uint2*>(&g_xh0[b * IN1])[i4] = h;
        reinterpret_cast<uint2*>(&g_xl0[b * IN1])[i4] = l;
        reinterpret_cast<uint2*>(&g_xh [b * IN2])[i4] = h;
        reinterpret_cast<uint2*>(&g_xl [b * IN2])[i4] = l;
        return;
    }
    idx -= nz;
    int nc = BSZ * (FRAME / 4);
    if (idx < nc) {
        int b = idx / (FRAME / 4), i4 = idx % (FRAME / 4);
        float4 v = reinterpret_cast<const float4*>(&c[b * FRAME])[i4];
        uint2 h, l; split4(v, h, l);
        reinterpret_cast<uint2*>(&g_xh0[b * IN1 + LAT])[i4] = h;
        reinterpret_cast<uint2*>(&g_xl0[b * IN1 + LAT])[i4] = l;
    }
}

// ---- weight prep: wt[(e*Nl+n)][k] = split(w[e][k][n]) --------------------
__global__ __launch_bounds__(256) void prep_kernel(
    const float* __restrict__ W, int Kw, int Nl)
{
    __shared__ float ts[32][33];
    const int k0  = blockIdx.x * 32;
    const int gn0 = blockIdx.y * 32;
    const int tx = threadIdx.x & 31, ty = threadIdx.x >> 5;
    const int e = gn0 / Nl, nl0 = gn0 - e * Nl;
    #pragma unroll
    for (int rr = 0; rr < 4; rr++) {
        int k = k0 + ty + rr * 8;
        ts[ty + rr * 8][tx] = W[((size_t)e * Kw + k) * Nl + nl0 + tx];
    }
    __syncthreads();
    #pragma unroll
    for (int rr = 0; rr < 4; rr++) {
        int n = ty + rr * 8;
        float v = ts[tx][n];
        __nv_bfloat16 h = __float2bfloat16(v);
        float lo = v - __bfloat162float(h);
        size_t off = (size_t)(gn0 + n) * Kw + k0 + tx;
        g_wth[off] = h;
        g_wtl[off] = __float2bfloat16(lo);
    }
}

// ---- mix: out[b,n] = act(sum_e coef*(Y[b,e,n] + bias[e,n])) --------------
// writes either fp32 d_out or bf16 hi/lo next-layer x at offset LAT.
__global__ void mix_kernel(
    const float* __restrict__ Y, const float* __restrict__ bias, int Nl,
    float* __restrict__ outf, __nv_bfloat16* __restrict__ oxh,
    __nv_bfloat16* __restrict__ oxl, int do_elu)
{
    int idx = blockIdx.x * blockDim.x + threadIdx.x;
    int nv = Nl / 4;
    if (idx >= BSZ * nv) return;
    int b = idx / nv, n4 = (idx - b * nv) * 4;
    const float* yb = Y + (size_t)b * (NE * Nl) + n4;
    float4 acc = make_float4(0.f, 0.f, 0.f, 0.f);
    #pragma unroll
    for (int e = 0; e < NE; e++) {
        float cf = g_coef[b * NE + e];
        float4 y = *reinterpret_cast<const float4*>(yb + (size_t)e * Nl);
        float4 bb = *reinterpret_cast<const float4*>(bias + e * Nl + n4);
        acc.x += cf * (y.x + bb.x);
        acc.y += cf * (y.y + bb.y);
        acc.z += cf * (y.z + bb.z);
        acc.w += cf * (y.w + bb.w);
    }
    if (do_elu) {
        acc.x = acc.x > 0.f ? acc.x : expm1f(acc.x);
        acc.y = acc.y > 0.f ? acc.y : expm1f(acc.y);
        acc.z = acc.z > 0.f ? acc.z : expm1f(acc.z);
        acc.w = acc.w > 0.f ? acc.w : expm1f(acc.w);
    }
    if (outf) {
        *reinterpret_cast<float4*>(outf + (size_t)b * Nl + n4) = acc;
    } else {
        uint2 h, l; split4(acc, h, l);
        *reinterpret_cast<uint2*>(oxh + (size_t)b * IN2 + LAT + n4) = h;
        *reinterpret_cast<uint2*>(oxl + (size_t)b * IN2 + LAT + n4) = l;
    }
}

// ======== split-bf16 mma.sync GEMM: Y = x @ Wflat, BM=BN=128, BK=32 =======
#define BMg 128
#define BNg 128
#define BKg 32
#define APITCH 40                  // bf16 per smem row (80B)
#define TILE_BF (128 * APITCH)     // 5120 bf16
#define STAGE_BF (4 * TILE_BF)     // Ah, Al, Bh, Bl
#define SMEM_BYTES (2 * STAGE_BF * 2)   // 81920

__global__ __launch_bounds__(256, 2) void gemm_mma_kernel(
    const __nv_bfloat16* __restrict__ xh, const __nv_bfloat16* __restrict__ xl,
    int xp, int Kw,
    const __nv_bfloat16* __restrict__ wth, const __nv_bfloat16* __restrict__ wtl,
    int Ntot, float* __restrict__ Y)
{
    extern __shared__ __nv_bfloat16 smem[];
    const uint32_t sb = smem_u32(smem);
    const int tid  = threadIdx.x;
    const int lane = tid & 31;
    const int wid  = tid >> 5;
    const int warp_m = wid & 3;
    const int warp_n = wid >> 2;
    const int bm = blockIdx.y * BMg;
    const int bn = blockIdx.x * BNg;

    float C[2][8][4];
    #pragma unroll
    for (int tm = 0; tm < 2; tm++)
        #pragma unroll
        for (int tn = 0; tn < 8; tn++)
            #pragma unroll
            for (int u = 0; u < 4; u++) C[tm][tn][u] = 0.f;

    // ldmatrix per-lane byte offsets (pitch 80B)
    const int a_r  = (lane & 7) + ((lane >> 3) & 1) * 8;
    const int a_ko = (lane >> 4) * 16;
    const uint32_t aoff = a_r * 80 + a_ko;
    const int b_r  = (lane & 7) + (lane >> 4) * 8;
    const int b_ko = ((lane >> 3) & 1) * 16;
    const uint32_t boff = b_r * 80 + b_ko;

    const int niter = Kw / BKg;

    // cp.async loader: 2 chunks/thread/tile, 16B each
    auto loadstage = [&](int it, int s) {
        const int k0 = it * BKg;
        const uint32_t stb = sb + s * (STAGE_BF * 2);
        #pragma unroll
        for (int j = 0; j < 2; j++) {
            int t = tid + j * 256;
            int row = t >> 2, q = t & 3;
            uint32_t so = (row * APITCH + q * 8) * 2;
            const __nv_bfloat16* a = xh + (size_t)(bm + row) * xp + k0 + q * 8;
            const __nv_bfloat16* al = xl + (size_t)(bm + row) * xp + k0 + q * 8;
            const __nv_bfloat16* bhp = wth + (size_t)(bn + row) * Kw + k0 + q * 8;
            const __nv_bfloat16* blp = wtl + (size_t)(bn + row) * Kw + k0 + q * 8;
            CP_ASYNC16(stb + so, a);
            CP_ASYNC16(stb + TILE_BF * 2 + so, al);
            CP_ASYNC16(stb + TILE_BF * 4 + so, bhp);
            CP_ASYNC16(stb + TILE_BF * 6 + so, blp);
        }
    };

    loadstage(0, 0);
    CP_COMMIT();

    for (int i = 0; i < niter; i++) {
        if (i + 1 < niter) loadstage(i + 1, (i + 1) & 1);
        CP_COMMIT();
        CP_WAIT1();
        __syncthreads();

        const int s = i & 1;
        const uint32_t sAh = sb + s * (STAGE_BF * 2);
        const uint32_t sAl = sAh + TILE_BF * 2;
        const uint32_t sBh = sAl + TILE_BF * 2;
        const uint32_t sBl = sBh + TILE_BF * 2;

        #pragma unroll
        for (int ks = 0; ks < 2; ks++) {
            uint32_t ah[2][4], al[2][4];
            #pragma unroll
            for (int tm = 0; tm < 2; tm++) {
                uint32_t base = (warp_m * 32 + tm * 16) * 80 + ks * 32;
                LDSM_X4(ah[tm][0], ah[tm][1], ah[tm][2], ah[tm][3], sAh + base + aoff);
                LDSM_X4(al[tm][0], al[tm][1], al[tm][2], al[tm][3], sAl + base + aoff);
            }
            #pragma unroll
            for (int g = 0; g < 4; g++) {
                uint32_t bh[4], bl[4];
                uint32_t base = (warp_n * 64 + g * 16) * 80 + ks * 32;
                LDSM_X4(bh[0], bh[1], bh[2], bh[3], sBh + base + boff);
                LDSM_X4(bl[0], bl[1], bl[2], bl[3], sBl + base + boff);
                #pragma unroll
                for (int tm = 0; tm < 2; tm++)
                    #pragma unroll
                    for (int half = 0; half < 2; half++) {
                        int tn = g * 2 + half;
                        const uint32_t* bph = &bh[half * 2];
                        const uint32_t* bpl = &bl[half * 2];
                        MMA_BF16(C[tm][tn], ah[tm], bph);
                        MMA_BF16(C[tm][tn], ah[tm], bpl);
                        MMA_BF16(C[tm][tn], al[tm], bph);
                    }
            }
        }
        __syncthreads();
    }

    // ---- epilogue: write Y fp32 ----
    #pragma unroll
    for (int tm = 0; tm < 2; tm++) {
        int m0 = bm + warp_m * 32 + tm * 16 + (lane >> 2);
        #pragma unroll
        for (int tn = 0; tn < 8; tn++) {
            int n0 = bn + warp_n * 64 + tn * 8 + (lane & 3) * 2;
            *reinterpret_cast<float2*>(Y + (size_t)m0 * Ntot + n0) =
                make_float2(C[tm][tn][0], C[tm][tn][1]);
            *reinterpret_cast<float2*>(Y + (size_t)(m0 + 8) * Ntot + n0) =
                make_float2(C[tm][tn][2], C[tm][tn][3]);
        }
    }
}

// ================================ launch ==================================
extern "C" void kernel_launch(void* const* d_in, const int* in_sizes, int n_in,
                              void* d_out, int out_size)
{
    const float* z   = (const float*)d_in[0];
    const float* c   = (const float*)d_in[1];
    const float* w0  = (const float*)d_in[2];
    const float* b0  = (const float*)d_in[3];
    const float* w1  = (const float*)d_in[4];
    const float* b1  = (const float*)d_in[5];
    const float* w2  = (const float*)d_in[6];
    const float* b2  = (const float*)d_in[7];
    const float* gw1 = (const float*)d_in[8];
    const float* gb1 = (const float*)d_in[9];
    const float* gw2 = (const float*)d_in[10];
    const float* gb2 = (const float*)d_in[11];
    const float* gw3 = (const float*)d_in[12];
    const float* gb3 = (const float*)d_in[13];
    float* out = (float*)d_out;

    __nv_bfloat16 *xh0, *xl0, *xh, *xl, *wth, *wtl;
    float *Y;
    cudaGetSymbolAddress((void**)&xh0, g_xh0);
    cudaGetSymbolAddress((void**)&xl0, g_xl0);
    cudaGetSymbolAddress((void**)&xh,  g_xh);
    cudaGetSymbolAddress((void**)&xl,  g_xl);
    cudaGetSymbolAddress((void**)&wth, g_wth);
    cudaGetSymbolAddress((void**)&wtl, g_wtl);
    cudaGetSymbolAddress((void**)&Y,   g_Y);

    cudaFuncSetAttribute(gemm_mma_kernel,
                         cudaFuncAttributeMaxDynamicSharedMemorySize, SMEM_BYTES);

    gate_kernel<<<BSZ / GROWS, 128>>>(z, c, gw1, gb1, gw2, gb2, gw3, gb3);
    {
        int total = BSZ * (LAT / 4) + BSZ * (FRAME / 4);
        fill_kernel<<<(total + 255) / 256, 256>>>(z, c);
    }

    const int NTOT1 = NE * HID;   // 8192
    const int NTOT2 = NE * NOUT;  // 4096
    const int mixthreads = 256;

    // ---- layer 0: Y = x0 @ W0flat; mix -> xh/xl ----
    {
        dim3 pg(IN1 / 32, NTOT1 / 32);
        prep_kernel<<<pg, 256>>>(w0, IN1, HID);
        dim3 grid(NTOT1 / BNg, BSZ / BMg);
        gemm_mma_kernel<<<grid, 256, SMEM_BYTES>>>(xh0, xl0, IN1, IN1,
                                                   wth, wtl, NTOT1, Y);
        int total = BSZ * (HID / 4);
        mix_kernel<<<(total + mixthreads - 1) / mixthreads, mixthreads>>>(
            Y, b0, HID, nullptr, xh, xl, 1);
    }
    // ---- layer 1 ----
    {
        dim3 pg(IN2 / 32, NTOT1 / 32);
        prep_kernel<<<pg, 256>>>(w1, IN2, HID);
        dim3 grid(NTOT1 / BNg, BSZ / BMg);
        gemm_mma_kernel<<<grid, 256, SMEM_BYTES>>>(xh, xl, IN2, IN2,
                                                   wth, wtl, NTOT1, Y);
        int total = BSZ * (HID / 4);
        mix_kernel<<<(total + mixthreads - 1) / mixthreads, mixthreads>>>(
            Y, b1, HID, nullptr, xh, xl, 1);
    }
    // ---- layer 2 ----
    {
        dim3 pg(IN2 / 32, NTOT2 / 32);
        prep_kernel<<<pg, 256>>>(w2, IN2, NOUT);
        dim3 grid(NTOT2 / BNg, BSZ / BMg);
        gemm_mma_kernel<<<grid, 256, SMEM_BYTES>>>(xh, xl, IN2, IN2,
                                                   wth, wtl, NTOT2, Y);
        int total = BSZ * (NOUT / 4);
        mix_kernel<<<(total + mixthreads - 1) / mixthreads, mixthreads>>>(
            Y, b2, NOUT, out, nullptr, nullptr, 0);
    }
}